// round 1
// baseline (speedup 1.0000x reference)
#include <cuda_runtime.h>

#define NH 18
#define NP 9   // float2 pairs per hidden vector

typedef unsigned long long u64;

__device__ __forceinline__ u64 pk2(float lo, float hi){
    u64 r; asm("mov.b64 %0, {%1,%2};" : "=l"(r) : "f"(lo), "f"(hi)); return r;
}
__device__ __forceinline__ u64 dup2(float v){
    u64 r; asm("mov.b64 %0, {%1,%1};" : "=l"(r) : "f"(v)); return r;
}
__device__ __forceinline__ void upk2(u64 v, float& lo, float& hi){
    asm("mov.b64 {%0,%1}, %2;" : "=f"(lo), "=f"(hi) : "l"(v));
}
__device__ __forceinline__ u64 fma2(u64 a, u64 b, u64 c){
    u64 d; asm("fma.rn.f32x2 %0, %1, %2, %3;" : "=l"(d) : "l"(a), "l"(b), "l"(c));
    return d;
}
// tanh(x) = 1 - 2/(exp(2x)+1), via MUFU.EX2 + MUFU.RCP. Accuracy ~1e-6,
// graceful saturation to +/-1 for large |x|.
__device__ __forceinline__ float fast_tanh(float x){
    float e;
    asm("ex2.approx.f32 %0, %1;" : "=f"(e) : "f"(x * 2.8853900817779268f));
    float r;
    asm("rcp.approx.f32 %0, %1;" : "=f"(r) : "f"(e + 1.0f));
    return fmaf(-2.0f, r, 1.0f);
}

// shared memory float offsets (all even -> 8B-aligned pairs)
#define S_WF   0      // Wf   [6][18]  = 108
#define S_WM   108    // Wm   [36][18] = 648
#define S_WUM  756    // Wu[0:18]       = 324
#define S_WUH  1080   // Wu[18:36]+Wu[36:54] = 324
#define S_WR   1404   // Wr   [90]
#define S_BF   1494   // 18
#define S_BM   1512   // 18
#define S_BU   1530   // 18
#define S_BR   1548   // 1
#define S_TOT  1550

__global__ void __launch_bounds__(128, 2) mp_kernel(
    const float* __restrict__ x,
    const float* __restrict__ Wf, const float* __restrict__ bf,
    const float* __restrict__ Wm, const float* __restrict__ bm,
    const float* __restrict__ Wu, const float* __restrict__ bu,
    const float* __restrict__ Wr, const float* __restrict__ br,
    float* __restrict__ out, int n)
{
    __shared__ __align__(16) float s[S_TOT];
    const int t = threadIdx.x;
    for (int k = t; k < 108; k += 128) s[S_WF + k] = Wf[k];
    for (int k = t; k < 648; k += 128) s[S_WM + k] = Wm[k];
    for (int k = t; k < 324; k += 128) s[S_WUM + k] = Wu[k];
    // fold Wu[18:36] + Wu[36:54] (u_in = [roll(M,1), h, h] since U==h there)
    for (int k = t; k < 324; k += 128) s[S_WUH + k] = Wu[324 + k] + Wu[648 + k];
    for (int k = t; k < 90;  k += 128) s[S_WR + k] = Wr[k];
    if (t < 18) { s[S_BF + t] = bf[t]; s[S_BM + t] = bm[t]; s[S_BU + t] = bu[t]; }
    if (t == 0) s[S_BR] = br[0];
    __syncthreads();

    const int b = blockIdx.x * 128 + t;
    if (b >= n) return;

    const u64* s2 = (const u64*)s;

    // ---- load x[b] : 30 floats, 8B-aligned (b*120 bytes) ----
    float xv[30];
    const float2* xb = (const float2*)(x + (long long)b * 30);
    #pragma unroll
    for (int k = 0; k < 15; k++) { float2 v = xb[k]; xv[2*k] = v.x; xv[2*k+1] = v.y; }

    // ---- layer 1: h = tanh(x @ Wf + bf), per node ----
    u64 acc[5][NP];
    #pragma unroll
    for (int p = 0; p < NP; p++) {
        u64 bp = s2[S_BF/2 + p];
        #pragma unroll
        for (int i = 0; i < 5; i++) acc[i][p] = bp;
    }
    #pragma unroll
    for (int f = 0; f < 6; f++) {
        u64 w[NP];
        #pragma unroll
        for (int p = 0; p < NP; p++) w[p] = s2[S_WF/2 + f*NP + p];
        #pragma unroll
        for (int i = 0; i < 5; i++) {
            u64 a = dup2(xv[i*6 + f]);
            #pragma unroll
            for (int p = 0; p < NP; p++) acc[i][p] = fma2(a, w[p], acc[i][p]);
        }
    }
    float h[5][NH];
    #pragma unroll
    for (int i = 0; i < 5; i++) {
        #pragma unroll
        for (int p = 0; p < NP; p++) {
            float lo, hi; upk2(acc[i][p], lo, hi);
            h[i][2*p]   = fast_tanh(lo);
            h[i][2*p+1] = fast_tanh(hi);
        }
    }

    // ---- layer M: M_i = tanh([h_i, h_{i+1}] @ Wm + bm) ----
    u64 am[5][NP];
    #pragma unroll
    for (int p = 0; p < NP; p++) {
        u64 bp = s2[S_BM/2 + p];
        #pragma unroll
        for (int i = 0; i < 5; i++) am[i][p] = bp;
    }
    #pragma unroll
    for (int e = 0; e < NH; e++) {               // h_i part: Wm rows [0,18)
        u64 w[NP];
        #pragma unroll
        for (int p = 0; p < NP; p++) w[p] = s2[S_WM/2 + e*NP + p];
        #pragma unroll
        for (int i = 0; i < 5; i++) {
            u64 a = dup2(h[i][e]);
            #pragma unroll
            for (int p = 0; p < NP; p++) am[i][p] = fma2(a, w[p], am[i][p]);
        }
    }
    #pragma unroll
    for (int e = 0; e < NH; e++) {               // h_{i+1} part: Wm rows [18,36)
        u64 w[NP];
        #pragma unroll
        for (int p = 0; p < NP; p++) w[p] = s2[S_WM/2 + (NH + e)*NP + p];
        #pragma unroll
        for (int i = 0; i < 5; i++) {
            u64 a = dup2(h[(i+1) % 5][e]);
            #pragma unroll
            for (int p = 0; p < NP; p++) am[i][p] = fma2(a, w[p], am[i][p]);
        }
    }
    float M[5][NH];
    #pragma unroll
    for (int i = 0; i < 5; i++) {
        #pragma unroll
        for (int p = 0; p < NP; p++) {
            float lo, hi; upk2(am[i][p], lo, hi);
            M[i][2*p]   = fast_tanh(lo);
            M[i][2*p+1] = fast_tanh(hi);
        }
    }

    // ---- layer U + readout:  U_i = tanh(M_{i-1} @ WuM + h_i @ WuH + bu),
    //      out = sum_i U_i @ Wr[i*18:(i+1)*18] + br ----
    u64 racc = 0;  // packed (0.0f, 0.0f)
    #pragma unroll
    for (int i = 0; i < 5; i++) {
        u64 au[NP];
        #pragma unroll
        for (int p = 0; p < NP; p++) au[p] = s2[S_BU/2 + p];
        #pragma unroll
        for (int e = 0; e < NH; e++) {
            u64 w[NP];
            #pragma unroll
            for (int p = 0; p < NP; p++) w[p] = s2[S_WUM/2 + e*NP + p];
            u64 a = dup2(M[(i + 4) % 5][e]);
            #pragma unroll
            for (int p = 0; p < NP; p++) au[p] = fma2(a, w[p], au[p]);
        }
        #pragma unroll
        for (int e = 0; e < NH; e++) {
            u64 w[NP];
            #pragma unroll
            for (int p = 0; p < NP; p++) w[p] = s2[S_WUH/2 + e*NP + p];
            u64 a = dup2(h[i][e]);
            #pragma unroll
            for (int p = 0; p < NP; p++) au[p] = fma2(a, w[p], au[p]);
        }
        #pragma unroll
        for (int p = 0; p < NP; p++) {
            float lo, hi; upk2(au[p], lo, hi);
            u64 U2 = pk2(fast_tanh(lo), fast_tanh(hi));
            racc = fma2(U2, s2[S_WR/2 + i*NP + p], racc);
        }
    }
    float r0, r1; upk2(racc, r0, r1);
    out[b] = r0 + r1 + s[S_BR];
}

extern "C" void kernel_launch(void* const* d_in, const int* in_sizes, int n_in,
                              void* d_out, int out_size)
{
    const float* x  = (const float*)d_in[0];
    const float* Wf = (const float*)d_in[1];
    const float* bf = (const float*)d_in[2];
    const float* Wm = (const float*)d_in[3];
    const float* bm = (const float*)d_in[4];
    const float* Wu = (const float*)d_in[5];
    const float* bu = (const float*)d_in[6];
    const float* Wr = (const float*)d_in[7];
    const float* br = (const float*)d_in[8];
    float* out = (float*)d_out;

    const int n = in_sizes[0] / 30;   // B (x is [B,5,6])
    const int blocks = (n + 127) / 128;
    mp_kernel<<<blocks, 128>>>(x, Wf, bf, Wm, bm, Wu, bu, Wr, br, out, n);
}